// round 2
// baseline (speedup 1.0000x reference)
#include <cuda_runtime.h>
#include <math.h>

#define D_MODEL 512
#define BATCH   4
#define SEQ     4096
#define HW      128              // half window ((257-1)/2)
#define ROWS    (BATCH * SEQ)    // 16384

// ---- scratch (static device arrays; no allocations allowed) ----
__device__ float g_Q[ROWS * D_MODEL];
__device__ float g_K[ROWS * D_MODEL];
__device__ float g_V[ROWS * D_MODEL];

// ============================================================================
// Projection GEMM: out = x @ W + b   (M=16384, N=512, K=512), z picks Q/K/V
// 128x128 block tile, BK=16, 256 threads, 8x8 per-thread micro-tile.
// ============================================================================
#define PBM 128
#define PBN 128
#define PBK 16
#define ASTRIDE 132   // padded [16][132] to reduce transpose-store conflicts

__global__ void __launch_bounds__(256) proj_kernel(
    const float* __restrict__ x,
    const float* __restrict__ Wq, const float* __restrict__ bq,
    const float* __restrict__ Wk, const float* __restrict__ bk,
    const float* __restrict__ Wv, const float* __restrict__ bv)
{
    const float* W; const float* bias; float* out;
    if (blockIdx.z == 0)      { W = Wq; bias = bq; out = g_Q; }
    else if (blockIdx.z == 1) { W = Wk; bias = bk; out = g_K; }
    else                      { W = Wv; bias = bv; out = g_V; }

    __shared__ float As[PBK * ASTRIDE];  // As[k][m]
    __shared__ float Bs[PBK * PBN];      // Bs[k][n]

    const int tid = threadIdx.x;
    const int tx = tid & 15;        // 0..15 -> 8 output cols each
    const int ty = tid >> 4;        // 0..15 -> 8 output rows each
    const int m0 = blockIdx.y * PBM;
    const int n0 = blockIdx.x * PBN;

    // A-load mapping: 128 rows x 16 cols, float4 along k
    const int arow = tid >> 2;            // 0..63
    const int acol = (tid & 3) * 4;       // 0,4,8,12
    // B-load mapping: 16 rows x 128 cols, float4 along n
    const int brow = tid >> 5;            // 0..7
    const int bcol = (tid & 31) * 4;      // 0..124

    float acc[8][8];
    #pragma unroll
    for (int i = 0; i < 8; i++)
        #pragma unroll
        for (int j = 0; j < 8; j++) acc[i][j] = 0.f;

    for (int k0 = 0; k0 < D_MODEL; k0 += PBK) {
        #pragma unroll
        for (int r = 0; r < 2; r++) {
            const float4 v = *(const float4*)&x[(size_t)(m0 + arow + r * 64) * D_MODEL + k0 + acol];
            As[(acol + 0) * ASTRIDE + arow + r * 64] = v.x;
            As[(acol + 1) * ASTRIDE + arow + r * 64] = v.y;
            As[(acol + 2) * ASTRIDE + arow + r * 64] = v.z;
            As[(acol + 3) * ASTRIDE + arow + r * 64] = v.w;
        }
        #pragma unroll
        for (int r = 0; r < 2; r++) {
            const float4 w = *(const float4*)&W[(size_t)(k0 + brow + r * 8) * D_MODEL + n0 + bcol];
            *(float4*)&Bs[(brow + r * 8) * PBN + bcol] = w;
        }
        __syncthreads();

        #pragma unroll
        for (int k = 0; k < PBK; k++) {
            float am[8], bn[8];
            #pragma unroll
            for (int i = 0; i < 8; i++) am[i] = As[k * ASTRIDE + ty * 8 + i];
            #pragma unroll
            for (int j = 0; j < 8; j++) bn[j] = Bs[k * PBN + tx * 8 + j];
            #pragma unroll
            for (int i = 0; i < 8; i++)
                #pragma unroll
                for (int j = 0; j < 8; j++) acc[i][j] += am[i] * bn[j];
        }
        __syncthreads();
    }

    #pragma unroll
    for (int i = 0; i < 8; i++) {
        const int gm = m0 + ty * 8 + i;
        #pragma unroll
        for (int j = 0; j < 8; j++) {
            const int gn = n0 + tx * 8 + j;
            out[(size_t)gm * D_MODEL + gn] = acc[i][j] + bias[gn];
        }
    }
}

// ============================================================================
// Banded attention: per block, 64-query tile of one batch. Keys in
// [q0-128, q0+63+128] (<=320). Dense 64x320 scores (register-accumulated over
// 8 D-chunks), masked softmax in smem, then P@V in 64-col D-chunks.
// ============================================================================
#define QT    64
#define NK    320
#define SPAD  321   // scores row stride (odd -> conflict-free column access)
#define KPAD  321   // Ks_t row stride
#define QPAD  65    // Qs_t row stride
#define DC    64    // D chunk

#define SM_FLOATS (QT * SPAD + DC * QPAD + DC * KPAD)

__global__ void __launch_bounds__(256) attn_kernel(float* __restrict__ outp)
{
    extern __shared__ float sm[];
    float* S_s = sm;                       // [64][SPAD]  scores / probs
    float* Qs  = sm + QT * SPAD;           // [DC][QPAD]  Q chunk transposed [d][m]
    float* KV  = Qs + DC * QPAD;           // union: Ks_t [DC][KPAD] or Vs [NK][DC]

    const int q0  = blockIdx.x * QT;
    const int b   = blockIdx.y;
    const int tid = threadIdx.x;
    const int tx  = tid & 15;   // 16 col-threads
    const int ty  = tid >> 4;   // 16 row-threads -> 4 rows each

    const float* Q = g_Q + (size_t)b * SEQ * D_MODEL;
    const float* K = g_K + (size_t)b * SEQ * D_MODEL;
    const float* V = g_V + (size_t)b * SEQ * D_MODEL;
    float*       O = outp + (size_t)b * SEQ * D_MODEL;

    const int jlo = (q0 - HW > 0) ? q0 - HW : 0;
    const int jhi_ = q0 + QT - 1 + HW;
    const int jhi = (jhi_ < SEQ - 1) ? jhi_ : SEQ - 1;
    const int nk  = jhi - jlo + 1;   // <= 320

    // ---------------- scores: acc[i][j] = Q[m] . K[n] ----------------
    float acc[4][20];
    #pragma unroll
    for (int i = 0; i < 4; i++)
        #pragma unroll
        for (int j = 0; j < 20; j++) acc[i][j] = 0.f;

    for (int d0 = 0; d0 < D_MODEL; d0 += DC) {
        for (int i = tid; i < QT * DC; i += 256) {
            const int m = i >> 6, dd = i & 63;
            Qs[dd * QPAD + m] = Q[(size_t)(q0 + m) * D_MODEL + d0 + dd];
        }
        for (int i = tid; i < NK * DC; i += 256) {
            const int j = i >> 6, dd = i & 63;
            KV[dd * KPAD + j] = (j < nk) ? K[(size_t)(jlo + j) * D_MODEL + d0 + dd] : 0.f;
        }
        __syncthreads();

        #pragma unroll 8
        for (int kk = 0; kk < DC; kk++) {
            float a[4], bb[20];
            #pragma unroll
            for (int i = 0; i < 4; i++) a[i] = Qs[kk * QPAD + ty * 4 + i];
            #pragma unroll
            for (int j = 0; j < 20; j++) bb[j] = KV[kk * KPAD + tx + j * 16];
            #pragma unroll
            for (int i = 0; i < 4; i++)
                #pragma unroll
                for (int j = 0; j < 20; j++) acc[i][j] += a[i] * bb[j];
        }
        __syncthreads();
    }

    // write masked, scaled scores
    const float scale = 0.044194173824159216f;   // 1/sqrt(512)
    #pragma unroll
    for (int i = 0; i < 4; i++) {
        const int m = ty * 4 + i;
        const int qi = q0 + m;
        #pragma unroll
        for (int j = 0; j < 20; j++) {
            const int n = tx + j * 16;
            const int kj = jlo + n;
            const int d = qi - kj;
            const bool valid = (n < nk) && (d <= HW) && (d >= -HW);
            S_s[m * SPAD + n] = valid ? acc[i][j] * scale : -INFINITY;
        }
    }
    __syncthreads();

    // ---------------- softmax (4 threads per row) ----------------
    {
        const int m = tid >> 2, sub = tid & 3;
        float mx = -INFINITY;
        for (int n = sub; n < NK; n += 4) mx = fmaxf(mx, S_s[m * SPAD + n]);
        mx = fmaxf(mx, __shfl_xor_sync(0xffffffffu, mx, 1));
        mx = fmaxf(mx, __shfl_xor_sync(0xffffffffu, mx, 2));
        float sum = 0.f;
        for (int n = sub; n < NK; n += 4) {
            const float e = __expf(S_s[m * SPAD + n] - mx);
            S_s[m * SPAD + n] = e;
            sum += e;
        }
        sum += __shfl_xor_sync(0xffffffffu, sum, 1);
        sum += __shfl_xor_sync(0xffffffffu, sum, 2);
        const float inv = 1.f / sum;
        for (int n = sub; n < NK; n += 4) S_s[m * SPAD + n] *= inv;
    }
    __syncthreads();

    // ---------------- out = P @ V, per 64-col D chunk ----------------
    for (int d0 = 0; d0 < D_MODEL; d0 += DC) {
        for (int i = tid; i < NK * DC; i += 256) {
            const int j = i >> 6, dd = i & 63;
            KV[j * DC + dd] = (j < nk) ? V[(size_t)(jlo + j) * D_MODEL + d0 + dd] : 0.f;
        }
        __syncthreads();

        float o[4][4];
        #pragma unroll
        for (int i = 0; i < 4; i++)
            #pragma unroll
            for (int j = 0; j < 4; j++) o[i][j] = 0.f;

        #pragma unroll 4
        for (int k = 0; k < NK; k++) {
            float p[4], vv[4];
            #pragma unroll
            for (int i = 0; i < 4; i++) p[i] = S_s[(ty * 4 + i) * SPAD + k];
            #pragma unroll
            for (int j = 0; j < 4; j++) vv[j] = KV[k * DC + tx + j * 16];
            #pragma unroll
            for (int i = 0; i < 4; i++)
                #pragma unroll
                for (int j = 0; j < 4; j++) o[i][j] += p[i] * vv[j];
        }

        #pragma unroll
        for (int i = 0; i < 4; i++) {
            const int gm = q0 + ty * 4 + i;
            #pragma unroll
            for (int j = 0; j < 4; j++)
                O[(size_t)gm * D_MODEL + d0 + tx + j * 16] = o[i][j];
        }
        __syncthreads();
    }
}

// ============================================================================
extern "C" void kernel_launch(void* const* d_in, const int* in_sizes, int n_in,
                              void* d_out, int out_size)
{
    const float* x  = (const float*)d_in[0];
    const float* Wq = (const float*)d_in[1];
    const float* bq = (const float*)d_in[2];
    const float* Wk = (const float*)d_in[3];
    const float* bk = (const float*)d_in[4];
    const float* Wv = (const float*)d_in[5];
    const float* bv = (const float*)d_in[6];
    float* out = (float*)d_out;

    dim3 gp(D_MODEL / PBN, ROWS / PBM, 3);
    proj_kernel<<<gp, 256>>>(x, Wq, bq, Wk, bk, Wv, bv);

    const size_t smem = (size_t)SM_FLOATS * sizeof(float);
    static int smem_set = 0;
    if (!smem_set) {
        cudaFuncSetAttribute(attn_kernel,
                             cudaFuncAttributeMaxDynamicSharedMemorySize, (int)smem);
        smem_set = 1;
    }
    attn_kernel<<<dim3(SEQ / QT, BATCH), 256, smem>>>(out);
}

// round 4
// speedup vs baseline: 1.4021x; 1.4021x over previous
#include <cuda_runtime.h>
#include <cuda_bf16.h>
#include <math.h>
#include <stdint.h>

#define D_MODEL 512
#define BATCH   4
#define SEQ     4096
#define HW      128
#define ROWS    (BATCH * SEQ)    // 16384

// ---- scratch (static device arrays; no allocations allowed) ----
__device__ float g_Q[ROWS * D_MODEL];
__device__ float g_K[ROWS * D_MODEL];
__device__ float g_V[ROWS * D_MODEL];
// bf16 split of x (hi/lo) as bf16x2 words, row-major [ROWS][256 words]
__device__ uint32_t g_xh[ROWS * 256];
__device__ uint32_t g_xl[ROWS * 256];
// W^T bf16 hi/lo as bf16x2 words, row-major [z][512 n][256 k-words]
__device__ uint32_t g_wth[3 * 512 * 256];
__device__ uint32_t g_wtl[3 * 512 * 256];

// ============================================================================
// helpers
// ============================================================================
__device__ __forceinline__ uint32_t smem_to_u32(const void* p) {
    uint32_t a;
    asm("{ .reg .u64 t; cvta.to.shared.u64 t, %1; cvt.u32.u64 %0, t; }" : "=r"(a) : "l"(p));
    return a;
}
__device__ __forceinline__ void cpa16(uint32_t dst, const void* src) {
    asm volatile("cp.async.cg.shared.global [%0], [%1], 16;" :: "r"(dst), "l"(src));
}
template <int N>
__device__ __forceinline__ void cpwait() {
    asm volatile("cp.async.wait_group %0;" :: "n"(N) : "memory");
}
__device__ __forceinline__ void cpcommit() {
    asm volatile("cp.async.commit_group;" ::: "memory");
}
__device__ __forceinline__ void ldm_x4(uint32_t* r, uint32_t addr) {
    asm volatile("ldmatrix.sync.aligned.m8n8.x4.shared.b16 {%0,%1,%2,%3}, [%4];"
                 : "=r"(r[0]), "=r"(r[1]), "=r"(r[2]), "=r"(r[3]) : "r"(addr));
}
__device__ __forceinline__ void mma_bf16(float* c, const uint32_t* a, const uint32_t* b) {
    asm volatile("mma.sync.aligned.m16n8k16.row.col.f32.bf16.bf16.f32 "
                 "{%0,%1,%2,%3}, {%4,%5,%6,%7}, {%8,%9}, {%0,%1,%2,%3};"
                 : "+f"(c[0]), "+f"(c[1]), "+f"(c[2]), "+f"(c[3])
                 : "r"(a[0]), "r"(a[1]), "r"(a[2]), "r"(a[3]), "r"(b[0]), "r"(b[1]));
}

// ============================================================================
// prep_x: split x rows into bf16 hi/lo pairs (row-major, k-major words)
// ============================================================================
__global__ void __launch_bounds__(256) prep_x_kernel(const float* __restrict__ x)
{
    const int m = blockIdx.x, p = threadIdx.x;
    const float2 v = *(const float2*)&x[(size_t)m * D_MODEL + 2 * p];
    __nv_bfloat162 hi2, lo2;
    hi2.x = __float2bfloat16_rn(v.x); hi2.y = __float2bfloat16_rn(v.y);
    lo2.x = __float2bfloat16_rn(v.x - __bfloat162float(hi2.x));
    lo2.y = __float2bfloat16_rn(v.y - __bfloat162float(hi2.y));
    g_xh[m * 256 + p] = *(uint32_t*)&hi2;
    g_xl[m * 256 + p] = *(uint32_t*)&lo2;
}

// ============================================================================
// prep_w: W^T bf16 hi/lo. grid = 3*512 (z,n); thread p packs k=2p,2p+1.
// ============================================================================
__global__ void __launch_bounds__(256) prep_w_kernel(
    const float* __restrict__ Wq, const float* __restrict__ Wk, const float* __restrict__ Wv)
{
    const int z = blockIdx.x >> 9, n = blockIdx.x & 511, p = threadIdx.x;
    const float* W = (z == 0) ? Wq : ((z == 1) ? Wk : Wv);
    const float w0 = W[(size_t)(2 * p) * D_MODEL + n];
    const float w1 = W[(size_t)(2 * p + 1) * D_MODEL + n];
    __nv_bfloat162 hi2, lo2;
    hi2.x = __float2bfloat16_rn(w0); hi2.y = __float2bfloat16_rn(w1);
    lo2.x = __float2bfloat16_rn(w0 - __bfloat162float(hi2.x));
    lo2.y = __float2bfloat16_rn(w1 - __bfloat162float(hi2.y));
    const size_t o = (size_t)(z * 512 + n) * 256 + p;
    g_wth[o] = *(uint32_t*)&hi2;
    g_wtl[o] = *(uint32_t*)&lo2;
}

// ============================================================================
// proj_mma: D[m][n] = sum_k A[m][k]*B[n][k] via mma.sync bf16 (3-part split),
// 128x128 tile, 24 stages of K=64, cp.async double-buffered.
// smem per buf: A [128][72 halves] + B [128][72 halves] = 36864B; x2 = 73728B.
// ============================================================================
#define PSTR_B 144                 // bytes per padded smem row (72 halves)
#define TILE_HALF_B (128 * PSTR_B) // 18432
#define BUF_B (2 * TILE_HALF_B)    // 36864
#define PROJ_SMEM (2 * BUF_B)      // 73728

__device__ __forceinline__ void proj_issue_stage(int s, uint32_t smem_base,
                                                 int m0, int n0, int z, int tid)
{
    const int part = s >> 3;
    const int k0w = (s & 7) * 32;                 // word offset within 256-word row
    const uint32_t* Asrc = (part < 2) ? g_xh : g_xl;
    const uint32_t* Bsrc = ((part == 1) ? g_wtl : g_wth) + (size_t)z * 512 * 256;
    const uint32_t abase = smem_base + (uint32_t)((s & 1) * BUF_B);
    const uint32_t bbase = abase + TILE_HALF_B;
    #pragma unroll
    for (int i = 0; i < 4; i++) {
        const int idx = i * 256 + tid;            // 0..1023
        const int row = idx >> 3, ch = idx & 7;   // 16B chunk
        cpa16(abase + row * PSTR_B + ch * 16, Asrc + (size_t)(m0 + row) * 256 + k0w + ch * 4);
        cpa16(bbase + row * PSTR_B + ch * 16, Bsrc + (size_t)(n0 + row) * 256 + k0w + ch * 4);
    }
    cpcommit();
}

__global__ void __launch_bounds__(256) proj_mma_kernel(
    const float* __restrict__ bq, const float* __restrict__ bk, const float* __restrict__ bv)
{
    extern __shared__ char smg[];
    const uint32_t smem_base = smem_to_u32(smg);
    const int tid = threadIdx.x;
    const int wid = tid >> 5, lane = tid & 31;
    const int nt = blockIdx.x, mt = blockIdx.y, z = blockIdx.z;
    const int m0 = mt * 128, n0 = nt * 128;
    float* out = (z == 0) ? g_Q : ((z == 1) ? g_K : g_V);
    const float* bias = (z == 0) ? bq : ((z == 1) ? bk : bv);

    const int wm = wid & 1;        // m half (64)
    const int wn = wid >> 1;       // n strip (32)

    float c[4][4][4];
    #pragma unroll
    for (int i = 0; i < 4; i++)
        #pragma unroll
        for (int j = 0; j < 4; j++)
            #pragma unroll
            for (int q = 0; q < 4; q++) c[i][j][q] = 0.f;

    // precomputed intra-tile offsets
    const int a_row = wm * 64 + (lane & 15);
    const int a_colh = (lane >> 4) * 8;                     // halves
    const int b_row = wn * 32 + (lane >> 4) * 8 + (lane & 7);
    const int b_colh = ((lane >> 3) & 1) * 8;               // halves

    proj_issue_stage(0, smem_base, m0, n0, z, tid);

    for (int s = 0; s < 24; s++) {
        if (s + 1 < 24) {
            proj_issue_stage(s + 1, smem_base, m0, n0, z, tid);
            cpwait<1>();
        } else {
            cpwait<0>();
        }
        __syncthreads();

        const uint32_t abase = smem_base + (uint32_t)((s & 1) * BUF_B);
        const uint32_t bbase = abase + TILE_HALF_B;

        #pragma unroll
        for (int kk = 0; kk < 4; kk++) {
            const int k0 = kk * 16;   // halves
            uint32_t af[4][4], bf[2][4];
            #pragma unroll
            for (int i = 0; i < 4; i++)
                ldm_x4(af[i], abase + (uint32_t)((a_row + i * 16) * PSTR_B + (k0 + a_colh) * 2));
            #pragma unroll
            for (int j = 0; j < 2; j++)
                ldm_x4(bf[j], bbase + (uint32_t)((b_row + j * 16) * PSTR_B + (k0 + b_colh) * 2));
            #pragma unroll
            for (int i = 0; i < 4; i++)
                #pragma unroll
                for (int j = 0; j < 4; j++)
                    mma_bf16(c[i][j], af[i], &bf[j >> 1][(j & 1) * 2]);
        }
        __syncthreads();
    }

    // epilogue
    #pragma unroll
    for (int i = 0; i < 4; i++) {
        const int gm = m0 + wm * 64 + i * 16 + (lane >> 2);
        #pragma unroll
        for (int j = 0; j < 4; j++) {
            const int gn = n0 + wn * 32 + j * 8 + (lane & 3) * 2;
            const float b0 = bias[gn], b1 = bias[gn + 1];
            float2 v0 = { c[i][j][0] + b0, c[i][j][1] + b1 };
            float2 v1 = { c[i][j][2] + b0, c[i][j][3] + b1 };
            *(float2*)&out[(size_t)gm * D_MODEL + gn] = v0;
            *(float2*)&out[(size_t)(gm + 8) * D_MODEL + gn] = v1;
        }
    }
}

// ============================================================================
// Banded attention (unchanged from passing R2 kernel)
// ============================================================================
#define QT    64
#define NK    320
#define SPAD  321
#define KPAD  321
#define QPAD  65
#define DC    64
#define SM_FLOATS (QT * SPAD + DC * QPAD + DC * KPAD)

__global__ void __launch_bounds__(256) attn_kernel(float* __restrict__ outp)
{
    extern __shared__ float sm[];
    float* S_s = sm;
    float* Qs  = sm + QT * SPAD;
    float* KV  = Qs + DC * QPAD;

    const int q0  = blockIdx.x * QT;
    const int b   = blockIdx.y;
    const int tid = threadIdx.x;
    const int tx  = tid & 15;
    const int ty  = tid >> 4;

    const float* Q = g_Q + (size_t)b * SEQ * D_MODEL;
    const float* K = g_K + (size_t)b * SEQ * D_MODEL;
    const float* V = g_V + (size_t)b * SEQ * D_MODEL;
    float*       O = outp + (size_t)b * SEQ * D_MODEL;

    const int jlo = (q0 - HW > 0) ? q0 - HW : 0;
    const int jhi_ = q0 + QT - 1 + HW;
    const int jhi = (jhi_ < SEQ - 1) ? jhi_ : SEQ - 1;
    const int nk  = jhi - jlo + 1;

    float acc[4][20];
    #pragma unroll
    for (int i = 0; i < 4; i++)
        #pragma unroll
        for (int j = 0; j < 20; j++) acc[i][j] = 0.f;

    for (int d0 = 0; d0 < D_MODEL; d0 += DC) {
        for (int i = tid; i < QT * DC; i += 256) {
            const int m = i >> 6, dd = i & 63;
            Qs[dd * QPAD + m] = Q[(size_t)(q0 + m) * D_MODEL + d0 + dd];
        }
        for (int i = tid; i < NK * DC; i += 256) {
            const int j = i >> 6, dd = i & 63;
            KV[dd * KPAD + j] = (j < nk) ? K[(size_t)(jlo + j) * D_MODEL + d0 + dd] : 0.f;
        }
        __syncthreads();

        #pragma unroll 8
        for (int kk = 0; kk < DC; kk++) {
            float a[4], bb[20];
            #pragma unroll
            for (int i = 0; i < 4; i++) a[i] = Qs[kk * QPAD + ty * 4 + i];
            #pragma unroll
            for (int j = 0; j < 20; j++) bb[j] = KV[kk * KPAD + tx + j * 16];
            #pragma unroll
            for (int i = 0; i < 4; i++)
                #pragma unroll
                for (int j = 0; j < 20; j++) acc[i][j] += a[i] * bb[j];
        }
        __syncthreads();
    }

    const float scale = 0.044194173824159216f;
    #pragma unroll
    for (int i = 0; i < 4; i++) {
        const int m = ty * 4 + i;
        const int qi = q0 + m;
        #pragma unroll
        for (int j = 0; j < 20; j++) {
            const int n = tx + j * 16;
            const int kj = jlo + n;
            const int d = qi - kj;
            const bool valid = (n < nk) && (d <= HW) && (d >= -HW);
            S_s[m * SPAD + n] = valid ? acc[i][j] * scale : -INFINITY;
        }
    }
    __syncthreads();

    {
        const int m = tid >> 2, sub = tid & 3;
        float mx = -INFINITY;
        for (int n = sub; n < NK; n += 4) mx = fmaxf(mx, S_s[m * SPAD + n]);
        mx = fmaxf(mx, __shfl_xor_sync(0xffffffffu, mx, 1));
        mx = fmaxf(mx, __shfl_xor_sync(0xffffffffu, mx, 2));
        float sum = 0.f;
        for (int n = sub; n < NK; n += 4) {
            const float e = __expf(S_s[m * SPAD + n] - mx);
            S_s[m * SPAD + n] = e;
            sum += e;
        }
        sum += __shfl_xor_sync(0xffffffffu, sum, 1);
        sum += __shfl_xor_sync(0xffffffffu, sum, 2);
        const float inv = 1.f / sum;
        for (int n = sub; n < NK; n += 4) S_s[m * SPAD + n] *= inv;
    }
    __syncthreads();

    for (int d0 = 0; d0 < D_MODEL; d0 += DC) {
        for (int i = tid; i < NK * DC; i += 256) {
            const int j = i >> 6, dd = i & 63;
            KV[j * DC + dd] = (j < nk) ? V[(size_t)(jlo + j) * D_MODEL + d0 + dd] : 0.f;
        }
        __syncthreads();

        float o[4][4];
        #pragma unroll
        for (int i = 0; i < 4; i++)
            #pragma unroll
            for (int j = 0; j < 4; j++) o[i][j] = 0.f;

        #pragma unroll 4
        for (int k = 0; k < NK; k++) {
            float p[4], vv[4];
            #pragma unroll
            for (int i = 0; i < 4; i++) p[i] = S_s[(ty * 4 + i) * SPAD + k];
            #pragma unroll
            for (int j = 0; j < 4; j++) vv[j] = KV[k * DC + tx + j * 16];
            #pragma unroll
            for (int i = 0; i < 4; i++)
                #pragma unroll
                for (int j = 0; j < 4; j++) o[i][j] += p[i] * vv[j];
        }

        #pragma unroll
        for (int i = 0; i < 4; i++) {
            const int gm = q0 + ty * 4 + i;
            #pragma unroll
            for (int j = 0; j < 4; j++)
                O[(size_t)gm * D_MODEL + d0 + tx + j * 16] = o[i][j];
        }
        __syncthreads();
    }
}

// ============================================================================
extern "C" void kernel_launch(void* const* d_in, const int* in_sizes, int n_in,
                              void* d_out, int out_size)
{
    const float* x  = (const float*)d_in[0];
    const float* Wq = (const float*)d_in[1];
    const float* bq = (const float*)d_in[2];
    const float* Wk = (const float*)d_in[3];
    const float* bk = (const float*)d_in[4];
    const float* Wv = (const float*)d_in[5];
    const float* bv = (const float*)d_in[6];
    float* out = (float*)d_out;

    static int attr_set = 0;
    if (!attr_set) {
        cudaFuncSetAttribute(attn_kernel, cudaFuncAttributeMaxDynamicSharedMemorySize,
                             (int)(SM_FLOATS * sizeof(float)));
        cudaFuncSetAttribute(proj_mma_kernel, cudaFuncAttributeMaxDynamicSharedMemorySize,
                             PROJ_SMEM);
        attr_set = 1;
    }

    prep_x_kernel<<<ROWS, 256>>>(x);
    prep_w_kernel<<<3 * 512, 256>>>(Wq, Wk, Wv);
    proj_mma_kernel<<<dim3(D_MODEL / 128, ROWS / 128, 3), 256, PROJ_SMEM>>>(bq, bk, bv);

    attn_kernel<<<dim3(SEQ / QT, BATCH), 256, SM_FLOATS * sizeof(float)>>>(out);
}

// round 5
// speedup vs baseline: 2.8592x; 2.0393x over previous
#include <cuda_runtime.h>
#include <cuda_bf16.h>
#include <math.h>
#include <stdint.h>

#define D_MODEL 512
#define BATCH   4
#define SEQ     4096
#define HW      128
#define ROWS    (BATCH * SEQ)    // 16384

// ---- scratch (static device arrays; no allocations allowed) ----
// bf16 split of x (hi/lo) as bf16x2 words, row-major [ROWS][256 words]
__device__ uint32_t g_xh[ROWS * 256];
__device__ uint32_t g_xl[ROWS * 256];
// W^T bf16 hi/lo as bf16x2 words, row-major [z][512 n][256 k-words]
__device__ uint32_t g_wth[3 * 512 * 256];
__device__ uint32_t g_wtl[3 * 512 * 256];
// Q,K bf16 hi/lo row-major [ROWS][256 words]
__device__ uint32_t g_Qh[ROWS * 256];
__device__ uint32_t g_Ql[ROWS * 256];
__device__ uint32_t g_Kh[ROWS * 256];
__device__ uint32_t g_Kl[ROWS * 256];
// V^T bf16 hi/lo: [b][d(512)][s-words(2048)] (+pad for window overread)
__device__ uint32_t g_Vth[4 * 512 * 2048 + 256];
__device__ uint32_t g_Vtl[4 * 512 * 2048 + 256];

// ============================================================================
// helpers
// ============================================================================
__device__ __forceinline__ uint32_t smem_to_u32(const void* p) {
    uint32_t a;
    asm("{ .reg .u64 t; cvta.to.shared.u64 t, %1; cvt.u32.u64 %0, t; }" : "=r"(a) : "l"(p));
    return a;
}
__device__ __forceinline__ void cpa16(uint32_t dst, const void* src) {
    asm volatile("cp.async.cg.shared.global [%0], [%1], 16;" :: "r"(dst), "l"(src));
}
template <int N>
__device__ __forceinline__ void cpwait() {
    asm volatile("cp.async.wait_group %0;" :: "n"(N) : "memory");
}
__device__ __forceinline__ void cpcommit() {
    asm volatile("cp.async.commit_group;" ::: "memory");
}
__device__ __forceinline__ void ldm_x4(uint32_t* r, uint32_t addr) {
    asm volatile("ldmatrix.sync.aligned.m8n8.x4.shared.b16 {%0,%1,%2,%3}, [%4];"
                 : "=r"(r[0]), "=r"(r[1]), "=r"(r[2]), "=r"(r[3]) : "r"(addr));
}
__device__ __forceinline__ void mma_bf16(float* c, const uint32_t* a, const uint32_t* b) {
    asm volatile("mma.sync.aligned.m16n8k16.row.col.f32.bf16.bf16.f32 "
                 "{%0,%1,%2,%3}, {%4,%5,%6,%7}, {%8,%9}, {%0,%1,%2,%3};"
                 : "+f"(c[0]), "+f"(c[1]), "+f"(c[2]), "+f"(c[3])
                 : "r"(a[0]), "r"(a[1]), "r"(a[2]), "r"(a[3]), "r"(b[0]), "r"(b[1]));
}
__device__ __forceinline__ void pack_hl(float v0, float v1, uint32_t& hi, uint32_t& lo) {
    __nv_bfloat162 h2, l2;
    h2.x = __float2bfloat16_rn(v0); h2.y = __float2bfloat16_rn(v1);
    l2.x = __float2bfloat16_rn(v0 - __bfloat162float(h2.x));
    l2.y = __float2bfloat16_rn(v1 - __bfloat162float(h2.y));
    hi = *(uint32_t*)&h2; lo = *(uint32_t*)&l2;
}

// ============================================================================
// prep_x / prep_w
// ============================================================================
__global__ void __launch_bounds__(256) prep_x_kernel(const float* __restrict__ x)
{
    const int m = blockIdx.x, p = threadIdx.x;
    const float2 v = *(const float2*)&x[(size_t)m * D_MODEL + 2 * p];
    uint32_t hi, lo;
    pack_hl(v.x, v.y, hi, lo);
    g_xh[m * 256 + p] = hi;
    g_xl[m * 256 + p] = lo;
}

__global__ void __launch_bounds__(256) prep_w_kernel(
    const float* __restrict__ Wq, const float* __restrict__ Wk, const float* __restrict__ Wv)
{
    const int z = blockIdx.x >> 9, n = blockIdx.x & 511, p = threadIdx.x;
    const float* W = (z == 0) ? Wq : ((z == 1) ? Wk : Wv);
    const float w0 = W[(size_t)(2 * p) * D_MODEL + n];
    const float w1 = W[(size_t)(2 * p + 1) * D_MODEL + n];
    uint32_t hi, lo;
    pack_hl(w0, w1, hi, lo);
    const size_t o = (size_t)(z * 512 + n) * 256 + p;
    g_wth[o] = hi;
    g_wtl[o] = lo;
}

// ============================================================================
// proj_mma: 128x128 tile, 24 stages, cp.async double buffer (validated R4).
// Epilogue now emits bf16 hi/lo (Q,K row-major; V transposed to [d][s]).
// ============================================================================
#define PSTR_B 144
#define TILE_HALF_B (128 * PSTR_B) // 18432
#define BUF_B (2 * TILE_HALF_B)    // 36864
#define PROJ_SMEM (2 * BUF_B)      // 73728

__device__ __forceinline__ void proj_issue_stage(int s, uint32_t smem_base,
                                                 int m0, int n0, int z, int tid)
{
    const int part = s >> 3;
    const int k0w = (s & 7) * 32;
    const uint32_t* Asrc = (part < 2) ? g_xh : g_xl;
    const uint32_t* Bsrc = ((part == 1) ? g_wtl : g_wth) + (size_t)z * 512 * 256;
    const uint32_t abase = smem_base + (uint32_t)((s & 1) * BUF_B);
    const uint32_t bbase = abase + TILE_HALF_B;
    #pragma unroll
    for (int i = 0; i < 4; i++) {
        const int idx = i * 256 + tid;
        const int row = idx >> 3, ch = idx & 7;
        cpa16(abase + row * PSTR_B + ch * 16, Asrc + (size_t)(m0 + row) * 256 + k0w + ch * 4);
        cpa16(bbase + row * PSTR_B + ch * 16, Bsrc + (size_t)(n0 + row) * 256 + k0w + ch * 4);
    }
    cpcommit();
}

__global__ void __launch_bounds__(256) proj_mma_kernel(
    const float* __restrict__ bq, const float* __restrict__ bk, const float* __restrict__ bv)
{
    extern __shared__ char smg[];
    const uint32_t smem_base = smem_to_u32(smg);
    const int tid = threadIdx.x;
    const int wid = tid >> 5, lane = tid & 31;
    const int nt = blockIdx.x, mt = blockIdx.y, z = blockIdx.z;
    const int m0 = mt * 128, n0 = nt * 128;
    const float* bias = (z == 0) ? bq : ((z == 1) ? bk : bv);

    const int wm = wid & 1;
    const int wn = wid >> 1;

    float c[4][4][4];
    #pragma unroll
    for (int i = 0; i < 4; i++)
        #pragma unroll
        for (int j = 0; j < 4; j++)
            #pragma unroll
            for (int q = 0; q < 4; q++) c[i][j][q] = 0.f;

    const int a_row = wm * 64 + (lane & 15);
    const int a_colh = (lane >> 4) * 8;
    const int b_row = wn * 32 + (lane >> 4) * 8 + (lane & 7);
    const int b_colh = ((lane >> 3) & 1) * 8;

    proj_issue_stage(0, smem_base, m0, n0, z, tid);

    for (int s = 0; s < 24; s++) {
        if (s + 1 < 24) {
            proj_issue_stage(s + 1, smem_base, m0, n0, z, tid);
            cpwait<1>();
        } else {
            cpwait<0>();
        }
        __syncthreads();

        const uint32_t abase = smem_base + (uint32_t)((s & 1) * BUF_B);
        const uint32_t bbase = abase + TILE_HALF_B;

        #pragma unroll
        for (int kk = 0; kk < 4; kk++) {
            const int k0 = kk * 16;
            uint32_t af[4][4], bf[2][4];
            #pragma unroll
            for (int i = 0; i < 4; i++)
                ldm_x4(af[i], abase + (uint32_t)((a_row + i * 16) * PSTR_B + (k0 + a_colh) * 2));
            #pragma unroll
            for (int j = 0; j < 2; j++)
                ldm_x4(bf[j], bbase + (uint32_t)((b_row + j * 16) * PSTR_B + (k0 + b_colh) * 2));
            #pragma unroll
            for (int i = 0; i < 4; i++)
                #pragma unroll
                for (int j = 0; j < 4; j++)
                    mma_bf16(c[i][j], af[i], &bf[j >> 1][(j & 1) * 2]);
        }
        __syncthreads();
    }

    if (z < 2) {
        uint32_t* oh = (z == 0) ? g_Qh : g_Kh;
        uint32_t* ol = (z == 0) ? g_Ql : g_Kl;
        #pragma unroll
        for (int i = 0; i < 4; i++) {
            const int gm = m0 + wm * 64 + i * 16 + (lane >> 2);
            #pragma unroll
            for (int j = 0; j < 4; j++) {
                const int gn = n0 + wn * 32 + j * 8 + (lane & 3) * 2;
                const float b0 = bias[gn], b1 = bias[gn + 1];
                uint32_t hi, lo;
                pack_hl(c[i][j][0] + b0, c[i][j][1] + b1, hi, lo);
                oh[(size_t)gm * 256 + gn / 2] = hi;
                ol[(size_t)gm * 256 + gn / 2] = lo;
                pack_hl(c[i][j][2] + b0, c[i][j][3] + b1, hi, lo);
                oh[(size_t)(gm + 8) * 256 + gn / 2] = hi;
                ol[(size_t)(gm + 8) * 256 + gn / 2] = lo;
            }
        }
    } else {
        // V: stage fp32 into smem [128][132], then pack transposed to [d][s]
        float* st = (float*)smg;
        #pragma unroll
        for (int i = 0; i < 4; i++) {
            const int r0 = wm * 64 + i * 16 + (lane >> 2);
            #pragma unroll
            for (int j = 0; j < 4; j++) {
                const int col = wn * 32 + j * 8 + (lane & 3) * 2;
                const float b0 = bias[n0 + col], b1 = bias[n0 + col + 1];
                st[r0 * 132 + col]           = c[i][j][0] + b0;
                st[r0 * 132 + col + 1]       = c[i][j][1] + b1;
                st[(r0 + 8) * 132 + col]     = c[i][j][2] + b0;
                st[(r0 + 8) * 132 + col + 1] = c[i][j][3] + b1;
            }
        }
        __syncthreads();
        const int bb2 = m0 >> 12;
        const int s0 = m0 & 4095;
        const int n = tid & 127, h = tid >> 7;
        const size_t obase = ((size_t)bb2 * 512 + n0 + n) * 2048 + (size_t)((s0 + h * 64) / 2);
        #pragma unroll
        for (int w = 0; w < 32; w++) {
            const int m = h * 64 + 2 * w;
            uint32_t hi, lo;
            pack_hl(st[m * 132 + n], st[(m + 1) * 132 + n], hi, lo);
            g_Vth[obase + w] = hi;
            g_Vtl[obase + w] = lo;
        }
    }
}

// ============================================================================
// attn_mma: per CTA 64 queries of one batch; keys window <= 320.
// Phase 1: S = Q.K^T (bf16 split, 24 stages). Softmax. P -> bf16 hi/lo smem.
// Phase 2: O = P.V (bf16 split, 2 N-halves x 15 stages).
// ============================================================================
#define NKEY   320
#define A1BUF  9216                 // 64*144
#define B1BUF  46080                // 320*144
#define PAIR1  (A1BUF + B1BUF)      // 55296
#define R1SZ   (2 * PAIR1)          // 110592
#define PH_OFF R1SZ                 // 110592
#define PL_OFF (R1SZ + 41984)       // 152576
#define ATT_SMEM (R1SZ + 2 * 41984) // 194560
#define PSTRW  164                  // P row stride in words (656B = 41*16B)
#define B2BUF  36864                // 256*144
#define SSTR   321                  // fp32 score row stride

__device__ __forceinline__ void attn_issue1(int s, uint32_t sb, int b, int q0,
                                            int jlo, int tid)
{
    const int part = s >> 3, dc = s & 7;
    const uint32_t* Asrc = ((part < 2) ? g_Qh : g_Ql) + (size_t)(b * SEQ + q0) * 256 + dc * 32;
    const uint32_t* Bsrc = ((part == 1) ? g_Kl : g_Kh) + (size_t)b * SEQ * 256 + dc * 32;
    const uint32_t ab = sb + (uint32_t)((s & 1) * PAIR1);
    const uint32_t bb = ab + A1BUF;
    #pragma unroll
    for (int t = 0; t < 2; t++) {
        const int idx = t * 256 + tid;
        const int row = idx >> 3, ch = idx & 7;
        cpa16(ab + row * 144 + ch * 16, Asrc + (size_t)row * 256 + ch * 4);
    }
    #pragma unroll
    for (int t = 0; t < 10; t++) {
        const int idx = t * 256 + tid;
        const int row = idx >> 3, ch = idx & 7;
        int jr = jlo + row; if (jr > SEQ - 1) jr = SEQ - 1;
        cpa16(bb + row * 144 + ch * 16, Bsrc + (size_t)jr * 256 + ch * 4);
    }
    cpcommit();
}

__device__ __forceinline__ void attn_issue2(int s, int nh, uint32_t sb, int b,
                                            int jlo, int tid)
{
    const int q = s / 5, kc = s % 5;
    const uint32_t* Bsrc = (q == 1) ? g_Vtl : g_Vth;
    const size_t base = (size_t)b * 512 * 2048 + (size_t)(jlo / 2 + kc * 32);
    const uint32_t bb = sb + (uint32_t)((s & 1) * B2BUF);
    #pragma unroll
    for (int t = 0; t < 8; t++) {
        const int idx = t * 256 + tid;
        const int row = idx >> 3, ch = idx & 7;
        cpa16(bb + row * 144 + ch * 16, Bsrc + base + (size_t)(nh * 256 + row) * 2048 + ch * 4);
    }
    cpcommit();
}

__global__ void __launch_bounds__(256) attn_mma_kernel(float* __restrict__ outp)
{
    extern __shared__ char smc[];
    const uint32_t sb = smem_to_u32(smc);
    float* S = (float*)smc;
    const int tid = threadIdx.x, wid = tid >> 5, lane = tid & 31;
    const int q0 = blockIdx.x * 64, b = blockIdx.y;
    const int jlo = (q0 - HW > 0) ? q0 - HW : 0;
    const int jhi = (q0 + 63 + HW < SEQ - 1) ? q0 + 63 + HW : SEQ - 1;
    const int nk = jhi - jlo + 1;
    const int wm = wid & 1, wn = wid >> 1;

    // ---------------- Phase 1: scores ----------------
    float c1[2][10][4];
    #pragma unroll
    for (int i = 0; i < 2; i++)
        #pragma unroll
        for (int j = 0; j < 10; j++)
            #pragma unroll
            for (int q = 0; q < 4; q++) c1[i][j][q] = 0.f;

    attn_issue1(0, sb, b, q0, jlo, tid);

    for (int s = 0; s < 24; s++) {
        if (s + 1 < 24) { attn_issue1(s + 1, sb, b, q0, jlo, tid); cpwait<1>(); }
        else            { cpwait<0>(); }
        __syncthreads();
        const uint32_t ab = sb + (uint32_t)((s & 1) * PAIR1);
        const uint32_t bb = ab + A1BUF;
        #pragma unroll
        for (int kk = 0; kk < 4; kk++) {
            uint32_t af[2][4], bf[5][4];
            #pragma unroll
            for (int i = 0; i < 2; i++)
                ldm_x4(af[i], ab + (uint32_t)((wm * 32 + i * 16 + (lane & 15)) * 144
                                              + (kk * 16 + (lane >> 4) * 8) * 2));
            #pragma unroll
            for (int jj = 0; jj < 5; jj++)
                ldm_x4(bf[jj], bb + (uint32_t)((wn * 80 + jj * 16 + (lane >> 4) * 8 + (lane & 7)) * 144
                                               + (kk * 16 + ((lane >> 3) & 1) * 8) * 2));
            #pragma unroll
            for (int i = 0; i < 2; i++)
                #pragma unroll
                for (int j = 0; j < 10; j++)
                    mma_bf16(c1[i][j], af[i], &bf[j >> 1][(j & 1) * 2]);
        }
        __syncthreads();
    }

    // masked, scaled scores -> smem (aliases phase-1 buffers; safe after waits)
    const float scale = 0.044194173824159216f;   // 1/sqrt(512)
    #pragma unroll
    for (int i = 0; i < 2; i++) {
        const int r = wm * 32 + i * 16 + (lane >> 2);
        #pragma unroll
        for (int j = 0; j < 10; j++) {
            const int n = wn * 80 + j * 8 + (lane & 3) * 2;
            #pragma unroll
            for (int reg = 0; reg < 4; reg++) {
                const int rr = r + ((reg >= 2) ? 8 : 0);
                const int nn = n + (reg & 1);
                const int d = (q0 + rr) - (jlo + nn);
                const bool valid = (nn < nk) && (d <= HW) && (d >= -HW);
                S[rr * SSTR + nn] = valid ? c1[i][j][reg] * scale : -INFINITY;
            }
        }
    }
    __syncthreads();

    // ---------------- softmax + P -> bf16 hi/lo ----------------
    {
        const int m = tid >> 2, sub = tid & 3;
        float mx = -INFINITY;
        for (int n = sub; n < NKEY; n += 4) mx = fmaxf(mx, S[m * SSTR + n]);
        mx = fmaxf(mx, __shfl_xor_sync(0xffffffffu, mx, 1));
        mx = fmaxf(mx, __shfl_xor_sync(0xffffffffu, mx, 2));
        float sum = 0.f;
        for (int n = sub; n < NKEY; n += 4) {
            const float e = __expf(S[m * SSTR + n] - mx);
            S[m * SSTR + n] = e;
            sum += e;
        }
        sum += __shfl_xor_sync(0xffffffffu, sum, 1);
        sum += __shfl_xor_sync(0xffffffffu, sum, 2);
        const float inv = 1.f / sum;
        __syncwarp();
        uint32_t* Ph = (uint32_t*)(smc + PH_OFF);
        uint32_t* Pl = (uint32_t*)(smc + PL_OFF);
        for (int w = sub; w < 160; w += 4) {
            const float p0 = S[m * SSTR + 2 * w] * inv;
            const float p1 = S[m * SSTR + 2 * w + 1] * inv;
            uint32_t hi, lo;
            pack_hl(p0, p1, hi, lo);
            Ph[m * PSTRW + w] = hi;
            Pl[m * PSTRW + w] = lo;
        }
    }
    __syncthreads();

    // ---------------- Phase 2: O = P @ V ----------------
    float* O = outp + ((size_t)b * SEQ + q0) * D_MODEL;
    for (int nh = 0; nh < 2; nh++) {
        float c2[2][8][4];
        #pragma unroll
        for (int i = 0; i < 2; i++)
            #pragma unroll
            for (int j = 0; j < 8; j++)
                #pragma unroll
                for (int q = 0; q < 4; q++) c2[i][j][q] = 0.f;

        attn_issue2(0, nh, sb, b, jlo, tid);
        for (int s = 0; s < 15; s++) {
            if (s + 1 < 15) { attn_issue2(s + 1, nh, sb, b, jlo, tid); cpwait<1>(); }
            else            { cpwait<0>(); }
            __syncthreads();
            const uint32_t bb = sb + (uint32_t)((s & 1) * B2BUF);
            const int kc = s % 5;
            const uint32_t pbase = sb + (uint32_t)(((s / 5) < 2) ? PH_OFF : PL_OFF);
            #pragma unroll
            for (int kk = 0; kk < 4; kk++) {
                uint32_t af[2][4], bf[4][4];
                #pragma unroll
                for (int i = 0; i < 2; i++)
                    ldm_x4(af[i], pbase + (uint32_t)((wm * 32 + i * 16 + (lane & 15)) * (PSTRW * 4)
                                   + (kc * 64 + kk * 16 + (lane >> 4) * 8) * 2));
                #pragma unroll
                for (int jj = 0; jj < 4; jj++)
                    ldm_x4(bf[jj], bb + (uint32_t)((wn * 64 + jj * 16 + (lane >> 4) * 8 + (lane & 7)) * 144
                                   + (kk * 16 + ((lane >> 3) & 1) * 8) * 2));
                #pragma unroll
                for (int i = 0; i < 2; i++)
                    #pragma unroll
                    for (int j = 0; j < 8; j++)
                        mma_bf16(c2[i][j], af[i], &bf[j >> 1][(j & 1) * 2]);
            }
            __syncthreads();
        }

        #pragma unroll
        for (int i = 0; i < 2; i++) {
            const int r = wm * 32 + i * 16 + (lane >> 2);
            #pragma unroll
            for (int j = 0; j < 8; j++) {
                const int dcol = nh * 256 + wn * 64 + j * 8 + (lane & 3) * 2;
                float2 v0 = { c2[i][j][0], c2[i][j][1] };
                float2 v1 = { c2[i][j][2], c2[i][j][3] };
                *(float2*)&O[(size_t)r * D_MODEL + dcol] = v0;
                *(float2*)&O[(size_t)(r + 8) * D_MODEL + dcol] = v1;
            }
        }
    }
}

// ============================================================================
extern "C" void kernel_launch(void* const* d_in, const int* in_sizes, int n_in,
                              void* d_out, int out_size)
{
    const float* x  = (const float*)d_in[0];
    const float* Wq = (const float*)d_in[1];
    const float* bq = (const float*)d_in[2];
    const float* Wk = (const float*)d_in[3];
    const float* bk = (const float*)d_in[4];
    const float* Wv = (const float*)d_in[5];
    const float* bv = (const float*)d_in[6];
    float* out = (float*)d_out;

    static int attr_set = 0;
    if (!attr_set) {
        cudaFuncSetAttribute(proj_mma_kernel, cudaFuncAttributeMaxDynamicSharedMemorySize,
                             PROJ_SMEM);
        cudaFuncSetAttribute(attn_mma_kernel, cudaFuncAttributeMaxDynamicSharedMemorySize,
                             ATT_SMEM);
        attr_set = 1;
    }

    prep_x_kernel<<<ROWS, 256>>>(x);
    prep_w_kernel<<<3 * 512, 256>>>(Wq, Wk, Wv);
    proj_mma_kernel<<<dim3(D_MODEL / 128, ROWS / 128, 3), 256, PROJ_SMEM>>>(bq, bk, bv);
    attn_mma_kernel<<<dim3(SEQ / 64, BATCH), 256, ATT_SMEM>>>(out);
}